// round 12
// baseline (speedup 1.0000x reference)
#include <cuda_runtime.h>
#include <cuda_bf16.h>
#include <cstdint>
#include <cstring>

// ============================ problem dims ============================
#define NHID   4096
#define BATCH  8192
#define NW     (NHID*NHID)       // 16,777,216 per score matrix
#define NH     (BATCH*NHID)      // 33,554,432 activation elements
#define NLAYER 5
#define TIE_CAP 16384

// GEMM tiling
#define BM 128
#define BN 128
#define BK 32
#define PITCH 40                 // smem row pitch in bf16 elems (80 B)
#define TILE_E (128*PITCH)       // elems per smem tile
#define NKC (NHID/BK)            // 128 k-chunks
#define GSMEM (6*TILE_E*2 + 512) // 3 tiles x 2 buffers + bias

// ============================ device scratch ============================
__device__ __align__(16) unsigned short g_a0h[NH];
__device__ __align__(16) unsigned short g_a0l[NH];
__device__ __align__(16) unsigned short g_a1h[NH];
__device__ __align__(16) unsigned short g_a1l[NH];
__device__ __align__(16) unsigned short g_w[NW];     // bf16 W for current layer
__device__ float    g_wo[2*NHID];                    // output-layer W (fp32)
__device__ int      g_hist[2048];
__device__ unsigned g_prefix;
__device__ int      g_rank;
__device__ unsigned g_T[2];
__device__ int      g_req[2];
__device__ int      g_tien[2];
__device__ int      g_tidx[2][TIE_CAP];
__device__ unsigned char g_tzero[2][TIE_CAP];

// ============================ small helpers ============================
static __device__ __forceinline__ unsigned short f2bf(float f) {
    __nv_bfloat16 b = __float2bfloat16(f);
    unsigned short u; memcpy(&u, &b, 2); return u;
}
static __device__ __forceinline__ float bf2f(unsigned short u) {
    __nv_bfloat16 b; memcpy(&b, &u, 2); return __bfloat162float(b);
}
static __device__ __forceinline__ void cpa16(uint32_t s, const void* g) {
    asm volatile("cp.async.cg.shared.global [%0], [%1], 16;" :: "r"(s), "l"(g));
}
static __device__ __forceinline__ void mma16816(float* c, const uint32_t* a, const uint32_t* b) {
    asm volatile(
        "mma.sync.aligned.m16n8k16.row.col.f32.bf16.bf16.f32 "
        "{%0,%1,%2,%3}, {%4,%5,%6,%7}, {%8,%9}, {%0,%1,%2,%3};"
        : "+f"(c[0]), "+f"(c[1]), "+f"(c[2]), "+f"(c[3])
        : "r"(a[0]), "r"(a[1]), "r"(a[2]), "r"(a[3]), "r"(b[0]), "r"(b[1]));
}

// ============================ mask selection ============================
__global__ void k_init(int j, int slot) {
    for (int i = threadIdx.x; i < 2048; i += blockDim.x) g_hist[i] = 0;
    if (threadIdx.x == 0) { g_prefix = 0u; g_rank = j; g_tien[slot] = 0; }
}

__global__ void k_hist(const float* __restrict__ s, int n, int shift, int width) {
    __shared__ int h[2048];
    for (int i = threadIdx.x; i < 2048; i += blockDim.x) h[i] = 0;
    __syncthreads();
    const unsigned pre = g_prefix;
    const int cs = shift + width;
    const unsigned msk = (1u << width) - 1u;
    for (int i = blockIdx.x * blockDim.x + threadIdx.x; i < n; i += gridDim.x * blockDim.x) {
        unsigned key = __float_as_uint(fabsf(s[i]));
        if ((key >> cs) == pre) atomicAdd(&h[(key >> shift) & msk], 1);
    }
    __syncthreads();
    for (int i = threadIdx.x; i < (1 << width); i += blockDim.x)
        if (h[i]) atomicAdd(&g_hist[i], h[i]);
}

__global__ void k_scan(int width, int last, int slot) {
    if (threadIdx.x == 0) {
        int r = g_rank;
        unsigned pre = g_prefix;
        const int nb = 1 << width;
        int cum = 0, sel = nb - 1;
        for (int b = 0; b < nb; b++) {
            int c = g_hist[b];
            if (cum + c >= r) { sel = b; r -= cum; break; }
            cum += c;
        }
        g_prefix = (pre << width) | (unsigned)sel;
        g_rank = r;
        if (last) { g_T[slot] = (pre << width) | (unsigned)sel; g_req[slot] = r; }
    }
    __syncthreads();
    for (int i = threadIdx.x; i < 2048; i += blockDim.x) g_hist[i] = 0;
}

__global__ void k_tiec(const float* __restrict__ s, int n, int slot) {
    const unsigned T = g_T[slot];
    for (int i = blockIdx.x * blockDim.x + threadIdx.x; i < n; i += gridDim.x * blockDim.x) {
        if (__float_as_uint(fabsf(s[i])) == T) {
            int p = atomicAdd(&g_tien[slot], 1);
            if (p < TIE_CAP) g_tidx[slot][p] = i;
        }
    }
}

__global__ void k_tier(int slot) {
    int t = g_tien[slot]; if (t > TIE_CAP) t = TIE_CAP;
    const int r = g_req[slot];
    for (int e = threadIdx.x; e < t; e += blockDim.x) {
        int me = g_tidx[slot][e];
        int c = 0;
        for (int o = 0; o < t; o++) c += (g_tidx[slot][o] < me);
        g_tzero[slot][e] = (c < r) ? 1 : 0;
    }
}

__global__ void k_buildw(const float* __restrict__ s1, const float* __restrict__ s2) {
    const unsigned T0 = g_T[0], T1 = g_T[1];
    const unsigned short bp1 = 0x3F80u, bm1 = 0xBF80u, bz = 0u;
    for (int i = blockIdx.x * blockDim.x + threadIdx.x; i < NW; i += gridDim.x * blockDim.x) {
        int m1 = (__float_as_uint(fabsf(s1[i])) >= T0);
        int m2 = (__float_as_uint(fabsf(s2[i])) >= T1);
        int v = m1 - m2;
        g_w[i] = (v > 0) ? bp1 : ((v < 0) ? bm1 : bz);
    }
}

__global__ void k_fixw(int slot, float delta) {
    int t = g_tien[slot]; if (t > TIE_CAP) t = TIE_CAP;
    for (int e = threadIdx.x; e < t; e += blockDim.x) {
        if (g_tzero[slot][e]) {
            int ix = g_tidx[slot][e];
            g_w[ix] = f2bf(bf2f(g_w[ix]) + delta);
        }
    }
}

__global__ void k_buildwo(const float* __restrict__ s1, const float* __restrict__ s2) {
    const unsigned T0 = g_T[0], T1 = g_T[1];
    for (int i = blockIdx.x * blockDim.x + threadIdx.x; i < 2 * NHID; i += gridDim.x * blockDim.x) {
        int m1 = (__float_as_uint(fabsf(s1[i])) >= T0);
        int m2 = (__float_as_uint(fabsf(s2[i])) >= T1);
        g_wo[i] = (float)(m1 - m2);
    }
}

__global__ void k_fixwo(int slot, float delta) {
    int t = g_tien[slot]; if (t > TIE_CAP) t = TIE_CAP;
    for (int e = threadIdx.x; e < t; e += blockDim.x) {
        if (g_tzero[slot][e]) g_wo[g_tidx[slot][e]] += delta;
    }
}

// ============================ activation split ============================
__global__ void k_split(const float* __restrict__ x) {
    for (int i = blockIdx.x * blockDim.x + threadIdx.x; i < NH; i += gridDim.x * blockDim.x) {
        float f = x[i];
        unsigned short h = f2bf(f);
        g_a0h[i] = h;
        g_a0l[i] = f2bf(f - bf2f(h));
    }
}

// ============================ fused GEMM layer (mma.sync bf16) ============================
// out[m,j] = relu( sum_k (hi[m,k]+lo[m,k]) * W[j,k] + 2*bias[j] ), re-split hi/lo.
__global__ void __launch_bounds__(256, 2) gemm5(int dir, const float* __restrict__ bias) {
    const unsigned short* __restrict__ Ahi = dir ? g_a1h : g_a0h;
    const unsigned short* __restrict__ Alo = dir ? g_a1l : g_a0l;
    unsigned short* __restrict__ Ohi = dir ? g_a0h : g_a1h;
    unsigned short* __restrict__ Olo = dir ? g_a0l : g_a1l;

    extern __shared__ unsigned short sm[];
    float* bias_s = (float*)(sm + 6 * TILE_E);
    const uint32_t smem_u = (uint32_t)__cvta_generic_to_shared(sm);

    const int tid = threadIdx.x, lid = tid & 31, wid = tid >> 5;
    const int n0 = blockIdx.x * BN;
    const int m0 = blockIdx.y * BM;
    const int wm = (wid & 3) * 32;       // warp m-offset within CTA tile
    const int wn = (wid >> 2) * 64;      // warp n-offset
    const int l4 = lid >> 2;             // 0..7
    const int lp = (lid & 3) * 2;        // 0,2,4,6

    if (tid < 128) bias_s[tid] = 2.0f * bias[n0 + tid];

    // loader mapping: idx = tid + rep*256 -> row = idx>>2 (0..127), seg = idx&3 (16B of 64B row)
    const int lr = tid >> 2, lsg = tid & 3;
    const unsigned short* gAh = Ahi + (size_t)(m0 + lr) * NHID + lsg * 8;
    const unsigned short* gAl = Alo + (size_t)(m0 + lr) * NHID + lsg * 8;
    const unsigned short* gW  = g_w + (size_t)(n0 + lr) * NHID + lsg * 8;
    const uint32_t s_off = (uint32_t)(lr * PITCH + lsg * 8) * 2u;

    // issue cp.async for k-chunk c into buffer buf
    auto issue = [&](int c, int buf) {
        const uint32_t sb = smem_u + (uint32_t)buf * (3u * TILE_E * 2u) + s_off;
        const size_t gk = (size_t)c * BK;
#pragma unroll
        for (int rep = 0; rep < 2; rep++) {
            const size_t go = gk + (size_t)rep * 64 * NHID;
            const uint32_t so = sb + (uint32_t)rep * 64u * PITCH * 2u;
            cpa16(so,                    gAh + go);
            cpa16(so + TILE_E * 2u,      gAl + go);
            cpa16(so + 2u * TILE_E * 2u, gW  + go);
        }
    };

    float acc[2][8][4];
#pragma unroll
    for (int mi = 0; mi < 2; mi++)
#pragma unroll
        for (int ni = 0; ni < 8; ni++)
#pragma unroll
            for (int q = 0; q < 4; q++) acc[mi][ni][q] = 0.0f;

    issue(0, 0);
    asm volatile("cp.async.commit_group;");

    for (int c = 0; c < NKC; ++c) {
        const int buf = c & 1;
        if (c + 1 < NKC) issue(c + 1, buf ^ 1);
        asm volatile("cp.async.commit_group;");
        asm volatile("cp.async.wait_group 1;");
        __syncthreads();

        const unsigned short* Sa = sm + buf * 3 * TILE_E;
        const unsigned short* Sl = Sa + TILE_E;
        const unsigned short* Sb = Sl + TILE_E;

#pragma unroll
        for (int ks = 0; ks < 2; ks++) {
            const int kb = ks * 16;
            uint32_t ah[2][4], al[2][4];
#pragma unroll
            for (int mi = 0; mi < 2; mi++) {
                const unsigned short* pr = Sa + (wm + mi * 16 + l4) * PITCH + kb + lp;
                const unsigned short* pl = Sl + (wm + mi * 16 + l4) * PITCH + kb + lp;
                ah[mi][0] = *(const uint32_t*)pr;
                ah[mi][1] = *(const uint32_t*)(pr + 8 * PITCH);
                ah[mi][2] = *(const uint32_t*)(pr + 8);
                ah[mi][3] = *(const uint32_t*)(pr + 8 * PITCH + 8);
                al[mi][0] = *(const uint32_t*)pl;
                al[mi][1] = *(const uint32_t*)(pl + 8 * PITCH);
                al[mi][2] = *(const uint32_t*)(pl + 8);
                al[mi][3] = *(const uint32_t*)(pl + 8 * PITCH + 8);
            }
#pragma unroll
            for (int ni = 0; ni < 8; ni++) {
                uint32_t bfr[2];
                const unsigned short* pb = Sb + (wn + ni * 8 + l4) * PITCH + kb + lp;
                bfr[0] = *(const uint32_t*)pb;
                bfr[1] = *(const uint32_t*)(pb + 8);
#pragma unroll
                for (int mi = 0; mi < 2; mi++) {
                    mma16816(acc[mi][ni], ah[mi], bfr);
                    mma16816(acc[mi][ni], al[mi], bfr);
                }
            }
        }
        __syncthreads();
    }

    // ---------------- epilogue: bias + relu + hi/lo split ----------------
#pragma unroll
    for (int mi = 0; mi < 2; mi++) {
#pragma unroll
        for (int ni = 0; ni < 8; ni++) {
            const int bidx = wn + ni * 8 + lp;
            const float b0 = bias_s[bidx], b1 = bias_s[bidx + 1];
            const int row0 = m0 + wm + mi * 16 + l4;
            const size_t col = (size_t)(n0 + bidx);
#pragma unroll
            for (int half = 0; half < 2; half++) {
                const int row = row0 + half * 8;
                float f0 = fmaxf(acc[mi][ni][2 * half]     + b0, 0.0f);
                float f1 = fmaxf(acc[mi][ni][2 * half + 1] + b1, 0.0f);
                unsigned short h0 = f2bf(f0), h1 = f2bf(f1);
                unsigned short e0 = f2bf(f0 - bf2f(h0)), e1 = f2bf(f1 - bf2f(h1));
                *(uint32_t*)(Ohi + (size_t)row * NHID + col) = (uint32_t)h0 | ((uint32_t)h1 << 16);
                *(uint32_t*)(Olo + (size_t)row * NHID + col) = (uint32_t)e0 | ((uint32_t)e1 << 16);
            }
        }
    }
}

// ============================ output layer + final ============================
__global__ void k_final(const float* __restrict__ bo, const float* __restrict__ wl,
                        float* __restrict__ out) {
    const int wid = threadIdx.x >> 5, lid = threadIdx.x & 31;
    const int m = blockIdx.x * 8 + wid;
    if (m >= BATCH) return;
    const unsigned short* ph = g_a1h + (size_t)m * NHID;
    const unsigned short* pl = g_a1l + (size_t)m * NHID;
    float s0 = 0.0f, s1 = 0.0f;
    for (int k = lid; k < NHID; k += 32) {
        float h = bf2f(ph[k]) + bf2f(pl[k]);
        s0 += h * g_wo[k];
        s1 += h * g_wo[NHID + k];
    }
#pragma unroll
    for (int o = 16; o > 0; o >>= 1) {
        s0 += __shfl_xor_sync(0xFFFFFFFFu, s0, o);
        s1 += __shfl_xor_sync(0xFFFFFFFFu, s1, o);
    }
    if (lid == 0) {
        float r0 = fmaxf(s0 + 2.0f * bo[0], 0.0f);
        float r1 = fmaxf(s1 + 2.0f * bo[1], 0.0f);
        out[m] = r0 * wl[0] + r1 * wl[1];
    }
}

// ============================ host orchestration ============================
static void run_select(const float* p, int n, int j, int slot) {
    int gb = (n >= (1 << 20)) ? 1024 : 32;
    k_init<<<1, 1024>>>(j, slot);
    k_hist<<<gb, 256>>>(p, n, 20, 11);
    k_scan<<<1, 256>>>(11, 0, slot);
    k_hist<<<gb, 256>>>(p, n, 10, 10);
    k_scan<<<1, 256>>>(10, 0, slot);
    k_hist<<<gb, 256>>>(p, n, 0, 10);
    k_scan<<<1, 256>>>(10, 1, slot);
    k_tiec<<<gb, 256>>>(p, n, slot);
    k_tier<<<1, 256>>>(slot);
}

extern "C" void kernel_launch(void* const* d_in, const int* in_sizes, int n_in,
                              void* d_out, int out_size) {
    (void)in_sizes; (void)n_in; (void)out_size;
    const float* x   = (const float*)d_in[0];
    const float* s1h = (const float*)d_in[1];
    const float* s2h = (const float*)d_in[2];
    const float* bh  = (const float*)d_in[3];
    const float* s1o = (const float*)d_in[4];
    const float* s2o = (const float*)d_in[5];
    const float* bo  = (const float*)d_in[6];
    const float* wl  = (const float*)d_in[7];
    float* out = (float*)d_out;

    cudaFuncSetAttribute((const void*)gemm5,
                         cudaFuncAttributeMaxDynamicSharedMemorySize, GSMEM);

    k_split<<<2048, 256>>>(x);

    for (int L = 0; L < NLAYER; ++L) {
        const float* p1 = s1h + (size_t)L * NW;
        const float* p2 = s2h + (size_t)L * NW;
        run_select(p1, NW, NW / 2, 0);
        run_select(p2, NW, NW / 2, 1);
        k_buildw<<<4096, 256>>>(p1, p2);
        k_fixw<<<1, 256>>>(0, -1.0f);
        k_fixw<<<1, 256>>>(1, +1.0f);
        gemm5<<<dim3(BN == 128 ? NHID / BN : 0, BATCH / BM), 256, GSMEM>>>(L & 1, bh + (size_t)L * NHID);
    }

    run_select(s1o, 2 * NHID, NHID, 0);
    run_select(s2o, 2 * NHID, NHID, 1);
    k_buildwo<<<32, 256>>>(s1o, s2o);
    k_fixwo<<<1, 256>>>(0, -1.0f);
    k_fixwo<<<1, 256>>>(1, +1.0f);
    k_final<<<BATCH / 8, 256>>>(bo, wl, out);
}